// round 15
// baseline (speedup 1.0000x reference)
#include <cuda_runtime.h>
#include <cuda_fp16.h>
#include <cstdint>

// ---------------------------------------------------------------------------
// LSTM Seq2Seq on GB300 — R15: lean-register split-K for 3 CTAs/SM.
// CTA 32m x 64n, grid 512, 256 thr = 8 warps = 2 K-halves x 4 n-groups,
// warp tile 32m x 16n. ~80 regs -> __launch_bounds__(256,3) -> 24 warps/SM.
// Layouts/setup identical to R13 (validated).
// ---------------------------------------------------------------------------

#define HIDDEN   512
#define BATCH    512
#define NFEAT    32
#define LAGS     96
#define HORIZONS 24
#define NGATE    2048

#define S_L0     17            // k32 stages, K=544
#define S_L1     32            // k32 stages, K=1024

#define BPK0_BYTES (256u * S_L0 * 512u)
#define BPK1_BYTES (256u * S_L1 * 512u)
#define HPK_BYTES  (32u * 32u * 512u)     // [mt 32][kt 32][512B]
#define XPK_T      (32u * 2u * 512u)      // [mt 32][ktl 2][512B] per timestep

// ---- scratch layout (bytes) ----
#define OFF_B0    0u
#define OFF_B1    (OFF_B0 + BPK0_BYTES)
#define OFF_B2    (OFF_B1 + BPK1_BYTES)
#define OFF_B3    (OFF_B2 + BPK0_BYTES)
#define OFF_BS    (OFF_B3 + BPK1_BYTES)            // float[4*2048]
#define OFF_H0PK  (OFF_BS + 4u * 2048u * 4u)       // 2 x HPK
#define OFF_H1PK  (OFF_H0PK + 2u * HPK_BYTES)      // 2 x HPK
#define OFF_C     (OFF_H1PK + 2u * HPK_BYTES)      // float[2*512*512]
#define OFF_XPK   (OFF_C + 2u * 512u * 512u * 4u)  // 96 x XPK_T
#define OFF_DECX  (OFF_XPK + 96u * XPK_T)          // XPK_T
#define OFF_H1PL  (OFF_DECX + XPK_T)               // half[512*512]
#define SCRATCH_BYTES (OFF_H1PL + 512u * 512u * 2u)

__device__ __align__(1024) unsigned char g_scratch[SCRATCH_BYTES];

// ---------------------------------------------------------------------------
__device__ __forceinline__ void mma_f16(float* d, const uint32_t* a,
                                        uint32_t b0, uint32_t b1) {
    asm volatile(
        "mma.sync.aligned.m16n8k16.row.col.f32.f16.f16.f32 "
        "{%0,%1,%2,%3},{%4,%5,%6,%7},{%8,%9},{%0,%1,%2,%3};"
        : "+f"(d[0]), "+f"(d[1]), "+f"(d[2]), "+f"(d[3])
        : "r"(a[0]), "r"(a[1]), "r"(a[2]), "r"(a[3]), "r"(b0), "r"(b1));
}
__device__ __forceinline__ float fsigmoid(float x) { return 1.f / (1.f + __expf(-x)); }
__device__ __forceinline__ float ftanh(float x)    { return 2.f / (1.f + __expf(-2.f * x)) - 1.f; }
__device__ __forceinline__ uint32_t h2u(float a, float b) {
    __half2 h = __floats2half2_rn(a, b);
    return *(uint32_t*)&h;
}

// ---------------------------------------------------------------------------
// Setup (launch #1): pack B (4 layers), biases, x (96 steps), zero states.
// (identical to R13)
// ---------------------------------------------------------------------------
struct WPtrs { const float* w[16]; };

__global__ void setup_all(const float* __restrict__ src, WPtrs wp)
{
    unsigned char* S = g_scratch;
    const int gs   = gridDim.x * blockDim.x;
    const int tid0 = blockIdx.x * blockDim.x + threadIdx.x;

    const uint32_t boff[4]  = {OFF_B0, OFF_B1, OFF_B2, OFF_B3};
    const int      bstg[4]  = {S_L0, S_L1, S_L0, S_L1};
    const int      indim[4] = {NFEAT, HIDDEN, NFEAT, HIDDEN};

    for (int l = 0; l < 4; ++l) {
        const float* Wih = wp.w[l * 4 + 0];
        const float* Whh = wp.w[l * 4 + 1];
        unsigned char* Bp = S + boff[l];
        const int stg = bstg[l], idim = indim[l];
        const int total = 256 * stg * 128;
        for (int u = tid0; u < total; u += gs) {
            int q    = u & 3;
            int lane = (u >> 2) & 31;
            int s    = (u >> 7) % stg;
            int nt   = (u >> 7) / stg;
            int n = nt * 8 + (lane >> 2);
            int k = s * 32 + q * 8 + 2 * (lane & 3);
            int j = n >> 2, g = n & 3;
            int row = g * HIDDEN + j;
            float v0, v1;
            if (k < idim)          v0 = Wih[row * idim + k];
            else                   v0 = Whh[row * HIDDEN + (k - idim)];
            if (k + 1 < idim)      v1 = Wih[row * idim + k + 1];
            else                   v1 = Whh[row * HIDDEN + (k + 1 - idim)];
            *(uint32_t*)(Bp + ((size_t)(nt * stg + s) * 32 + lane) * 16 + q * 4) = h2u(v0, v1);
        }
        const float* bih = wp.w[l * 4 + 2];
        const float* bhh = wp.w[l * 4 + 3];
        float* BS = (float*)(S + OFF_BS);
        for (int n = tid0; n < NGATE; n += gs) {
            int j = n >> 2, g = n & 3;
            BS[l * NGATE + n] = bih[g * HIDDEN + j] + bhh[g * HIDDEN + j];
        }
    }

    {   // x fragment packing: [t][mt 32][ktl 2][lane 32][q 4]
        unsigned char* Xp = S + OFF_XPK;
        const int total = LAGS * 32 * 2 * 128;
        for (int u = tid0; u < total; u += gs) {
            int q    = u & 3;
            int lane = (u >> 2) & 31;
            int ktl  = (u >> 7) & 1;
            int mt   = (u >> 8) & 31;
            int t    = (u >> 13);
            int m = mt * 16 + (q & 1) * 8 + (lane >> 2);
            int k = ktl * 16 + (q >> 1) * 8 + 2 * (lane & 3);
            float v0 = src[m * (LAGS * NFEAT) + t * NFEAT + k];
            float v1 = src[m * (LAGS * NFEAT) + t * NFEAT + k + 1];
            *(uint32_t*)(Xp + (size_t)t * XPK_T +
                         ((size_t)(mt * 2 + ktl) * 32 + lane) * 16 + q * 4) = h2u(v0, v1);
        }
    }

    {   // zero h-packed (4 buffers), c, h1plain
        uint32_t* Z = (uint32_t*)(S + OFF_H0PK);
        int total = (4 * HPK_BYTES + 2 * 512 * 512 * 4) / 4;
        for (int i = tid0; i < total; i += gs) Z[i] = 0;
        uint32_t* P = (uint32_t*)(S + OFF_H1PL);
        for (int i = tid0; i < 512 * 512 * 2 / 4; i += gs) P[i] = 0;
    }
}

// launch #2: initial decx (packed) from src[:, 95, :]  (identical to R13)
__global__ void init_decx_pk(const float* __restrict__ src)
{
    unsigned char* Dp = g_scratch + OFF_DECX;
    int u = blockIdx.x * blockDim.x + threadIdx.x;
    if (u >= 32 * 2 * 128) return;
    int q    = u & 3;
    int lane = (u >> 2) & 31;
    int ktl  = (u >> 7) & 1;
    int mt   = (u >> 8);
    int m = mt * 16 + (q & 1) * 8 + (lane >> 2);
    int k = ktl * 16 + (q >> 1) * 8 + 2 * (lane & 3);
    float v0 = src[m * (LAGS * NFEAT) + (LAGS - 1) * NFEAT + k];
    float v1 = src[m * (LAGS * NFEAT) + (LAGS - 1) * NFEAT + k + 1];
    *(uint32_t*)(Dp + ((size_t)(mt * 2 + ktl) * 32 + lane) * 16 + q * 4) = h2u(v0, v1);
}

// ---------------------------------------------------------------------------
// Split-K mainloop half: stages [S0, S1), warp tile 32m x 16n.
// Per warp per stage: 4 A-LDG.128 + 2 B-LDG.128 -> 8 MMA.
// ---------------------------------------------------------------------------
template <int S0, int S1, int XKT, int S>
__device__ __forceinline__
void run_half(const unsigned char* __restrict__ xp,
              const unsigned char* __restrict__ hp,
              const unsigned char* __restrict__ bptr,
              int mtb, int lane, float acc[2][2][4])
{
    uint4 a[2][2][2];     // [buf][mt][kt-parity]
    uint4 b[2][2];        // [buf][nt]

    auto loadS = [&](int buf, int s) {
        const int kt0 = 2 * s;
        const unsigned char* base;
        int ktl0, mts;
        if (kt0 < XKT) { base = xp; ktl0 = kt0;       mts = XKT * 512; }
        else           { base = hp; ktl0 = kt0 - XKT; mts = 32 * 512;  }
#pragma unroll
        for (int i = 0; i < 2; ++i) {
            const unsigned char* p = base + (size_t)(mtb + i) * mts + (size_t)ktl0 * 512 + lane * 16;
            a[buf][i][0] = *(const uint4*)p;
            a[buf][i][1] = *(const uint4*)(p + 512);
        }
#pragma unroll
        for (int j = 0; j < 2; ++j)
            b[buf][j] = *(const uint4*)(bptr + ((size_t)j * S + s) * 512);
    };

    loadS(0, S0);
#pragma unroll 4
    for (int i = 0; i < S1 - S0; ++i) {
        const int s  = S0 + i;
        const int cb = i & 1;
        if (s + 1 < S1) loadS(cb ^ 1, s + 1);
#pragma unroll
        for (int mi = 0; mi < 2; ++mi)
#pragma unroll
            for (int nf = 0; nf < 2; ++nf) {
                mma_f16(acc[mi][nf], (const uint32_t*)&a[cb][mi][0], b[cb][nf].x, b[cb][nf].y);
                mma_f16(acc[mi][nf], (const uint32_t*)&a[cb][mi][1], b[cb][nf].z, b[cb][nf].w);
            }
    }
}

// ---------------------------------------------------------------------------
// Direct-LDG split-K GEMM + fused LSTM cell.
// grid(32, 16): x = n64-tile (16 j), y = m32-tile. 256 threads = 8 warps:
// half = w>>2 (K half), wl = w&3 (n-group), warp tile 32m x 16n.
// ---------------------------------------------------------------------------
template <int S, int XKT, bool WPLAIN>
__global__ __launch_bounds__(256, 3)
void lstm_step_dl(const unsigned char* __restrict__ xp,  // packed, mt-stride XKT*512
                  const unsigned char* __restrict__ hp,  // packed, mt-stride 32*512
                  const unsigned char* __restrict__ Bp,
                  const float* __restrict__ bs,
                  float* __restrict__ cst,
                  unsigned char* __restrict__ hop,       // packed h out
                  __half* __restrict__ hplain)
{
    constexpr int SH = (S + 1) / 2;

    const int tid  = threadIdx.x;
    const int w    = tid >> 5, lane = tid & 31;
    const int half = w >> 2, wl = w & 3;
    const int mtb  = blockIdx.y * 2;                     // 2 mt tiles (32 m rows)
    const int ntb  = blockIdx.x * 8 + wl * 2;            // 2 nt tiles (16 n)
    const int g    = lane >> 2, tg = lane & 3;

    const unsigned char* bptr = Bp + ((size_t)ntb * S * 32 + lane) * 16;

    float acc[2][2][4];
#pragma unroll
    for (int i = 0; i < 2; ++i)
#pragma unroll
        for (int nf = 0; nf < 2; ++nf)
#pragma unroll
            for (int q = 0; q < 4; ++q) acc[i][nf][q] = 0.f;

    if (half == 0) run_half<0,  SH, XKT, S>(xp, hp, bptr, mtb, lane, acc);
    else           run_half<SH, S,  XKT, S>(xp, hp, bptr, mtb, lane, acc);

    // ---- epilogue: half0 writes z, half1 adds, then fused cell ----
    __shared__ float zs[32 * 68];

    if (half == 0) {
#pragma unroll
        for (int mi = 0; mi < 2; ++mi)
#pragma unroll
            for (int nf = 0; nf < 2; ++nf) {
                int r = mi * 16 + g;
                int c = wl * 16 + nf * 8 + 2 * tg;
                *(float2*)&zs[r * 68 + c]       = make_float2(acc[mi][nf][0], acc[mi][nf][1]);
                *(float2*)&zs[(r + 8) * 68 + c] = make_float2(acc[mi][nf][2], acc[mi][nf][3]);
            }
    }
    __syncthreads();
    if (half == 1) {
#pragma unroll
        for (int mi = 0; mi < 2; ++mi)
#pragma unroll
            for (int nf = 0; nf < 2; ++nf) {
                int r = mi * 16 + g;
                int c = wl * 16 + nf * 8 + 2 * tg;
                float2* p0 = (float2*)&zs[r * 68 + c];
                float2* p1 = (float2*)&zs[(r + 8) * 68 + c];
                float2 v0 = *p0, v1 = *p1;
                v0.x += acc[mi][nf][0]; v0.y += acc[mi][nf][1];
                v1.x += acc[mi][nf][2]; v1.y += acc[mi][nf][3];
                *p0 = v0; *p1 = v1;
            }
    }
    __syncthreads();

    {   // 256 threads: row = tid>>3 (0..31), grp = tid&7 (2 j each)
        const int row = tid >> 3;
        const int grp = tid & 7;
        const int bg  = blockIdx.y * 32 + row;     // global batch row
        const int j0  = blockIdx.x * 16 + grp * 2; // global j (2 consecutive)
        const int n0  = blockIdx.x * 64 + grp * 8;

        const float* zrow = &zs[row * 68 + grp * 8];
        float2 cA = *(const float2*)&cst[bg * HIDDEN + j0];
        float cOld[2] = {cA.x, cA.y};
        float hv[2], cN[2];
#pragma unroll
        for (int q = 0; q < 2; ++q) {
            float4 z4 = *(const float4*)&zrow[q * 4];
            float4 b4 = *(const float4*)&bs[n0 + q * 4];
            float zi = z4.x + b4.x;
            float zf = z4.y + b4.y;
            float zg = z4.z + b4.z;
            float zo = z4.w + b4.w;
            float cn = fsigmoid(zf) * cOld[q] + fsigmoid(zi) * ftanh(zg);
            cN[q] = cn;
            hv[q] = fsigmoid(zo) * ftanh(cn);
        }
        *(float2*)&cst[bg * HIDDEN + j0] = make_float2(cN[0], cN[1]);

        // packed h store: 2 consecutive j = one u32 in fragment layout
        {
            int kt = j0 >> 4, kkb = j0 & 15;
            int mt = bg >> 4, r = bg & 15;
            int q  = ((r >> 3) & 1) + ((kkb >> 3) & 1) * 2;
            int l0 = ((r & 7) << 2) + ((kkb & 7) >> 1);
            *(uint32_t*)(hop + ((size_t)(mt * 32 + kt) * 32 + l0) * 16 + q * 4) =
                h2u(hv[0], hv[1]);
        }
        if (WPLAIN) {
            __half2 p0 = __floats2half2_rn(hv[0], hv[1]);
            *(uint32_t*)&hplain[bg * HIDDEN + j0] = *(uint32_t*)&p0;
        }
    }
}

// ---------------------------------------------------------------------------
// Decoder heads: out[b][t] = h1·fc1 + b1 ; decx_packed = h1·fc4^T + b4
// (identical to R13)
// ---------------------------------------------------------------------------
__global__ __launch_bounds__(256)
void dec_fc(const __half* __restrict__ h1,
            const float* __restrict__ fc1_w, const float* __restrict__ fc1_b,
            const float* __restrict__ fc4_w, const float* __restrict__ fc4_b,
            float* __restrict__ out, int t)
{
    unsigned char* Dp = g_scratch + OFF_DECX;
    __shared__ float sh[HIDDEN];
    const int b = blockIdx.x;
    for (int i = threadIdx.x; i < HIDDEN; i += blockDim.x)
        sh[i] = __half2float(h1[b * HIDDEN + i]);
    __syncthreads();

    const int warp = threadIdx.x >> 5;
    const int lane = threadIdx.x & 31;
    for (int o = warp; o < 1 + NFEAT; o += 8) {
        const float* w = (o == 0) ? fc1_w : (fc4_w + (o - 1) * HIDDEN);
        float s = 0.f;
#pragma unroll 4
        for (int k = lane; k < HIDDEN; k += 32) s += sh[k] * w[k];
#pragma unroll
        for (int off = 16; off; off >>= 1) s += __shfl_down_sync(0xffffffffu, s, off);
        if (lane == 0) {
            if (o == 0) {
                out[b * HORIZONS + t] = s + fc1_b[0];
            } else {
                int f = o - 1;
                float v = s + fc4_b[f];
                int ktl = f >> 4, kk = f & 15;
                int mt = b >> 4, r = b & 15;
                int q  = ((r >> 3) & 1) + ((kk >> 3) & 1) * 2;
                int l0 = ((r & 7) << 2) + ((kk & 7) >> 1);
                unsigned char* addr = Dp + ((size_t)(mt * 2 + ktl) * 32 + l0) * 16
                                      + q * 4 + (kk & 1) * 2;
                *(__half*)addr = __float2half_rn(v);
            }
        }
    }
}

// ---------------------------------------------------------------------------
extern "C" void kernel_launch(void* const* d_in, const int* in_sizes, int n_in,
                              void* d_out, int out_size)
{
    const int wb = (in_sizes[2] == 1) ? 3 : 2;

    const float* src = (const float*)d_in[0];
    WPtrs wp;
    for (int i = 0; i < 16; i++) wp.w[i] = (const float*)d_in[wb + i];
    const float* fc1_w = (const float*)d_in[wb + 16];
    const float* fc1_b = (const float*)d_in[wb + 17];
    const float* fc4_w = (const float*)d_in[wb + 18];
    const float* fc4_b = (const float*)d_in[wb + 19];
    float* out = (float*)d_out;

    unsigned char* S = nullptr;
    cudaGetSymbolAddress((void**)&S, g_scratch);

    unsigned char* B0 = S + OFF_B0;
    unsigned char* B1 = S + OFF_B1;
    unsigned char* B2 = S + OFF_B2;
    unsigned char* B3 = S + OFF_B3;
    float* BS = (float*)(S + OFF_BS);
    unsigned char* H0PK[2] = {S + OFF_H0PK, S + OFF_H0PK + HPK_BYTES};
    unsigned char* H1PK[2] = {S + OFF_H1PK, S + OFF_H1PK + HPK_BYTES};
    float* C0 = (float*)(S + OFF_C);
    float* C1 = C0 + 512 * 512;
    unsigned char* XPK  = S + OFF_XPK;
    unsigned char* DECX = S + OFF_DECX;
    __half* H1PL = (__half*)(S + OFF_H1PL);

    // launch #1, #2  ->  ncu -s 5 lands on launch #6 = l1(t=1)
    setup_all<<<1024, 256>>>(src, wp);
    init_decx_pk<<<(32 * 2 * 128 + 255) / 256, 256>>>(src);

    dim3 grid(32, 16);   // 512 CTAs, 256 threads each

    for (int t = 0; t < LAGS; t++) {
        lstm_step_dl<S_L0, 2, false><<<grid, 256>>>(
            XPK + (size_t)t * XPK_T, H0PK[t & 1], B0, BS + 0 * NGATE,
            C0, H0PK[(t + 1) & 1], nullptr);
        lstm_step_dl<S_L1, 32, false><<<grid, 256>>>(
            H0PK[(t + 1) & 1], H1PK[t & 1], B1, BS + 1 * NGATE,
            C1, H1PK[(t + 1) & 1], nullptr);
    }

    for (int tt = 0; tt < HORIZONS; tt++) {
        int t = LAGS + tt;
        lstm_step_dl<S_L0, 2, false><<<grid, 256>>>(
            DECX, H0PK[t & 1], B2, BS + 2 * NGATE,
            C0, H0PK[(t + 1) & 1], nullptr);
        lstm_step_dl<S_L1, 32, true><<<grid, 256>>>(
            H0PK[(t + 1) & 1], H1PK[t & 1], B3, BS + 3 * NGATE,
            C1, H1PK[(t + 1) & 1], H1PL);
        dec_fc<<<BATCH, 256>>>(H1PL, fc1_w, fc1_b, fc4_w, fc4_b, out, tt);
    }
}

// round 16
// speedup vs baseline: 1.4352x; 1.4352x over previous
#include <cuda_runtime.h>
#include <cuda_fp16.h>
#include <cstdint>

// ---------------------------------------------------------------------------
// LSTM Seq2Seq on GB300 — R16 = R13 (split-K direct-LDG fp16 mma) + fused
// encoder wave: one launch runs l1(t-1) (blockIdx.z=0) and l0(t) (z=1)
// concurrently; they are buffer-disjoint. Decoder unchanged from R13.
// ---------------------------------------------------------------------------

#define HIDDEN   512
#define BATCH    512
#define NFEAT    32
#define LAGS     96
#define HORIZONS 24
#define NGATE    2048

#define S_L0     17            // k32 stages, K=544
#define S_L1     32            // k32 stages, K=1024

#define BPK0_BYTES (256u * S_L0 * 512u)
#define BPK1_BYTES (256u * S_L1 * 512u)
#define HPK_BYTES  (32u * 32u * 512u)     // [mt 32][kt 32][512B]
#define XPK_T      (32u * 2u * 512u)      // [mt 32][ktl 2][512B] per timestep

// ---- scratch layout (bytes) ----
#define OFF_B0    0u
#define OFF_B1    (OFF_B0 + BPK0_BYTES)
#define OFF_B2    (OFF_B1 + BPK1_BYTES)
#define OFF_B3    (OFF_B2 + BPK0_BYTES)
#define OFF_BS    (OFF_B3 + BPK1_BYTES)            // float[4*2048]
#define OFF_H0PK  (OFF_BS + 4u * 2048u * 4u)       // 2 x HPK
#define OFF_H1PK  (OFF_H0PK + 2u * HPK_BYTES)      // 2 x HPK
#define OFF_C     (OFF_H1PK + 2u * HPK_BYTES)      // float[2*512*512]
#define OFF_XPK   (OFF_C + 2u * 512u * 512u * 4u)  // 96 x XPK_T
#define OFF_DECX  (OFF_XPK + 96u * XPK_T)          // XPK_T
#define OFF_H1PL  (OFF_DECX + XPK_T)               // half[512*512]
#define SCRATCH_BYTES (OFF_H1PL + 512u * 512u * 2u)

__device__ __align__(1024) unsigned char g_scratch[SCRATCH_BYTES];

// ---------------------------------------------------------------------------
__device__ __forceinline__ void mma_f16(float* d, const uint32_t* a,
                                        uint32_t b0, uint32_t b1) {
    asm volatile(
        "mma.sync.aligned.m16n8k16.row.col.f32.f16.f16.f32 "
        "{%0,%1,%2,%3},{%4,%5,%6,%7},{%8,%9},{%0,%1,%2,%3};"
        : "+f"(d[0]), "+f"(d[1]), "+f"(d[2]), "+f"(d[3])
        : "r"(a[0]), "r"(a[1]), "r"(a[2]), "r"(a[3]), "r"(b0), "r"(b1));
}
__device__ __forceinline__ float fsigmoid(float x) { return 1.f / (1.f + __expf(-x)); }
__device__ __forceinline__ float ftanh(float x)    { return 2.f / (1.f + __expf(-2.f * x)) - 1.f; }
__device__ __forceinline__ uint32_t h2u(float a, float b) {
    __half2 h = __floats2half2_rn(a, b);
    return *(uint32_t*)&h;
}

// ---------------------------------------------------------------------------
// Setup (launch #1): pack B (4 layers), biases, x (96 steps), zero states.
// ---------------------------------------------------------------------------
struct WPtrs { const float* w[16]; };

__global__ void setup_all(const float* __restrict__ src, WPtrs wp)
{
    unsigned char* S = g_scratch;
    const int gs   = gridDim.x * blockDim.x;
    const int tid0 = blockIdx.x * blockDim.x + threadIdx.x;

    const uint32_t boff[4]  = {OFF_B0, OFF_B1, OFF_B2, OFF_B3};
    const int      bstg[4]  = {S_L0, S_L1, S_L0, S_L1};
    const int      indim[4] = {NFEAT, HIDDEN, NFEAT, HIDDEN};

    for (int l = 0; l < 4; ++l) {
        const float* Wih = wp.w[l * 4 + 0];
        const float* Whh = wp.w[l * 4 + 1];
        unsigned char* Bp = S + boff[l];
        const int stg = bstg[l], idim = indim[l];
        const int total = 256 * stg * 128;
        for (int u = tid0; u < total; u += gs) {
            int q    = u & 3;
            int lane = (u >> 2) & 31;
            int s    = (u >> 7) % stg;
            int nt   = (u >> 7) / stg;
            int n = nt * 8 + (lane >> 2);
            int k = s * 32 + q * 8 + 2 * (lane & 3);
            int j = n >> 2, g = n & 3;
            int row = g * HIDDEN + j;
            float v0, v1;
            if (k < idim)          v0 = Wih[row * idim + k];
            else                   v0 = Whh[row * HIDDEN + (k - idim)];
            if (k + 1 < idim)      v1 = Wih[row * idim + k + 1];
            else                   v1 = Whh[row * HIDDEN + (k + 1 - idim)];
            *(uint32_t*)(Bp + ((size_t)(nt * stg + s) * 32 + lane) * 16 + q * 4) = h2u(v0, v1);
        }
        const float* bih = wp.w[l * 4 + 2];
        const float* bhh = wp.w[l * 4 + 3];
        float* BS = (float*)(S + OFF_BS);
        for (int n = tid0; n < NGATE; n += gs) {
            int j = n >> 2, g = n & 3;
            BS[l * NGATE + n] = bih[g * HIDDEN + j] + bhh[g * HIDDEN + j];
        }
    }

    {   // x fragment packing: [t][mt 32][ktl 2][lane 32][q 4]
        unsigned char* Xp = S + OFF_XPK;
        const int total = LAGS * 32 * 2 * 128;
        for (int u = tid0; u < total; u += gs) {
            int q    = u & 3;
            int lane = (u >> 2) & 31;
            int ktl  = (u >> 7) & 1;
            int mt   = (u >> 8) & 31;
            int t    = (u >> 13);
            int m = mt * 16 + (q & 1) * 8 + (lane >> 2);
            int k = ktl * 16 + (q >> 1) * 8 + 2 * (lane & 3);
            float v0 = src[m * (LAGS * NFEAT) + t * NFEAT + k];
            float v1 = src[m * (LAGS * NFEAT) + t * NFEAT + k + 1];
            *(uint32_t*)(Xp + (size_t)t * XPK_T +
                         ((size_t)(mt * 2 + ktl) * 32 + lane) * 16 + q * 4) = h2u(v0, v1);
        }
    }

    {   // zero h-packed (4 buffers), c, h1plain
        uint32_t* Z = (uint32_t*)(S + OFF_H0PK);
        int total = (4 * HPK_BYTES + 2 * 512 * 512 * 4) / 4;
        for (int i = tid0; i < total; i += gs) Z[i] = 0;
        uint32_t* P = (uint32_t*)(S + OFF_H1PL);
        for (int i = tid0; i < 512 * 512 * 2 / 4; i += gs) P[i] = 0;
    }
}

// launch #2: initial decx (packed) from src[:, 95, :]
__global__ void init_decx_pk(const float* __restrict__ src)
{
    unsigned char* Dp = g_scratch + OFF_DECX;
    int u = blockIdx.x * blockDim.x + threadIdx.x;
    if (u >= 32 * 2 * 128) return;
    int q    = u & 3;
    int lane = (u >> 2) & 31;
    int ktl  = (u >> 7) & 1;
    int mt   = (u >> 8);
    int m = mt * 16 + (q & 1) * 8 + (lane >> 2);
    int k = ktl * 16 + (q >> 1) * 8 + 2 * (lane & 3);
    float v0 = src[m * (LAGS * NFEAT) + (LAGS - 1) * NFEAT + k];
    float v1 = src[m * (LAGS * NFEAT) + (LAGS - 1) * NFEAT + k + 1];
    *(uint32_t*)(Dp + ((size_t)(mt * 2 + ktl) * 32 + lane) * 16 + q * 4) = h2u(v0, v1);
}

// ---------------------------------------------------------------------------
// Split-K mainloop half: stages [S0, S1), warp tile 32m x 32n.
// ---------------------------------------------------------------------------
template <int S0, int S1, int XKT, int S>
__device__ __forceinline__
void run_half(const unsigned char* __restrict__ xp,
              const unsigned char* __restrict__ hp,
              const unsigned char* __restrict__ bptr,
              int mtb, int lane, float acc[2][4][4])
{
    uint4 a[2][2][2];
    uint4 b[2][4];

    auto loadS = [&](int buf, int s) {
        const int kt0 = 2 * s;
        const unsigned char* base;
        int ktl0, mts;
        if (kt0 < XKT) { base = xp; ktl0 = kt0;       mts = XKT * 512; }
        else           { base = hp; ktl0 = kt0 - XKT; mts = 32 * 512;  }
#pragma unroll
        for (int i = 0; i < 2; ++i) {
            const unsigned char* p = base + (size_t)(mtb + i) * mts + (size_t)ktl0 * 512 + lane * 16;
            a[buf][i][0] = *(const uint4*)p;
            a[buf][i][1] = *(const uint4*)(p + 512);
        }
#pragma unroll
        for (int j = 0; j < 4; ++j)
            b[buf][j] = *(const uint4*)(bptr + ((size_t)j * S + s) * 512);
    };

    loadS(0, S0);
#pragma unroll 4
    for (int i = 0; i < S1 - S0; ++i) {
        const int s  = S0 + i;
        const int cb = i & 1;
        if (s + 1 < S1) loadS(cb ^ 1, s + 1);
#pragma unroll
        for (int mi = 0; mi < 2; ++mi)
#pragma unroll
            for (int nf = 0; nf < 4; ++nf) {
                mma_f16(acc[mi][nf], (const uint32_t*)&a[cb][mi][0], b[cb][nf].x, b[cb][nf].y);
                mma_f16(acc[mi][nf], (const uint32_t*)&a[cb][mi][1], b[cb][nf].z, b[cb][nf].w);
            }
    }
}

// ---------------------------------------------------------------------------
// GEMM + cell body (R13, as device function; bx/by passed in).
// ---------------------------------------------------------------------------
template <int S, int XKT, bool WPLAIN>
__device__ __forceinline__
void gemm_body(float* zs, int bx, int by,
               const unsigned char* __restrict__ xp,
               const unsigned char* __restrict__ hp,
               const unsigned char* __restrict__ Bp,
               const float* __restrict__ bs,
               float* __restrict__ cst,
               unsigned char* __restrict__ hop,
               __half* __restrict__ hplain)
{
    constexpr int SH = (S + 1) / 2;

    const int tid  = threadIdx.x;
    const int w    = tid >> 5, lane = tid & 31;
    const int half = w >> 2, wl = w & 3;
    const int mgrp = wl >> 1, ngrp = wl & 1;
    const int mtb  = by * 4 + mgrp * 2;
    const int ntb  = bx * 8 + ngrp * 4;
    const int g    = lane >> 2, tg = lane & 3;

    const unsigned char* bptr = Bp + ((size_t)ntb * S * 32 + lane) * 16;

    float acc[2][4][4];
#pragma unroll
    for (int i = 0; i < 2; ++i)
#pragma unroll
        for (int nf = 0; nf < 4; ++nf)
#pragma unroll
            for (int q = 0; q < 4; ++q) acc[i][nf][q] = 0.f;

    if (half == 0) run_half<0,  SH, XKT, S>(xp, hp, bptr, mtb, lane, acc);
    else           run_half<SH, S,  XKT, S>(xp, hp, bptr, mtb, lane, acc);

    if (half == 0) {
#pragma unroll
        for (int i = 0; i < 2; ++i)
#pragma unroll
            for (int nf = 0; nf < 4; ++nf) {
                int r = mgrp * 32 + i * 16 + g;
                int c = ngrp * 32 + nf * 8 + 2 * tg;
                *(float2*)&zs[r * 68 + c]       = make_float2(acc[i][nf][0], acc[i][nf][1]);
                *(float2*)&zs[(r + 8) * 68 + c] = make_float2(acc[i][nf][2], acc[i][nf][3]);
            }
    }
    __syncthreads();
    if (half == 1) {
#pragma unroll
        for (int i = 0; i < 2; ++i)
#pragma unroll
            for (int nf = 0; nf < 4; ++nf) {
                int r = mgrp * 32 + i * 16 + g;
                int c = ngrp * 32 + nf * 8 + 2 * tg;
                float2* p0 = (float2*)&zs[r * 68 + c];
                float2* p1 = (float2*)&zs[(r + 8) * 68 + c];
                float2 v0 = *p0, v1 = *p1;
                v0.x += acc[i][nf][0]; v0.y += acc[i][nf][1];
                v1.x += acc[i][nf][2]; v1.y += acc[i][nf][3];
                *p0 = v0; *p1 = v1;
            }
    }
    __syncthreads();

    {   // 256 threads: row = tid>>2 (0..63), grp = tid&3 (4 j each)
        const int row = tid >> 2;
        const int grp = tid & 3;
        const int bg  = by * 64 + row;
        const int j0  = bx * 16 + grp * 4;
        const int n0  = bx * 64 + grp * 16;

        const float* zrow = &zs[row * 68 + grp * 16];
        float4 cA = *(const float4*)&cst[bg * HIDDEN + j0];
        float cOld[4] = {cA.x, cA.y, cA.z, cA.w};
        float hv[4], cN[4];
#pragma unroll
        for (int q = 0; q < 4; ++q) {
            float4 z4 = *(const float4*)&zrow[q * 4];
            float4 b4 = *(const float4*)&bs[n0 + q * 4];
            float zi = z4.x + b4.x;
            float zf = z4.y + b4.y;
            float zg = z4.z + b4.z;
            float zo = z4.w + b4.w;
            float cn = fsigmoid(zf) * cOld[q] + fsigmoid(zi) * ftanh(zg);
            cN[q] = cn;
            hv[q] = fsigmoid(zo) * ftanh(cn);
        }
        *(float4*)&cst[bg * HIDDEN + j0] = make_float4(cN[0], cN[1], cN[2], cN[3]);

        {
            int kt = j0 >> 4, kkb = j0 & 15;
            int mt = bg >> 4, r = bg & 15;
            int q  = ((r >> 3) & 1) + ((kkb >> 3) & 1) * 2;
            int l0 = ((r & 7) << 2) + ((kkb & 7) >> 1);
            unsigned char* base = hop + ((size_t)(mt * 32 + kt) * 32 + l0) * 16 + q * 4;
            *(uint32_t*)base        = h2u(hv[0], hv[1]);
            *(uint32_t*)(base + 16) = h2u(hv[2], hv[3]);
        }
        if (WPLAIN) {
            __half2 p0 = __floats2half2_rn(hv[0], hv[1]);
            __half2 p1 = __floats2half2_rn(hv[2], hv[3]);
            *(uint2*)&hplain[bg * HIDDEN + j0] =
                make_uint2(*(uint32_t*)&p0, *(uint32_t*)&p1);
        }
    }
}

// ---------------------------------------------------------------------------
// Standalone kernel (decoder + encoder edges)
// ---------------------------------------------------------------------------
template <int S, int XKT, bool WPLAIN>
__global__ __launch_bounds__(256, 2)
void lstm_step_dl(const unsigned char* __restrict__ xp,
                  const unsigned char* __restrict__ hp,
                  const unsigned char* __restrict__ Bp,
                  const float* __restrict__ bs,
                  float* __restrict__ cst,
                  unsigned char* __restrict__ hop,
                  __half* __restrict__ hplain)
{
    __shared__ float zs[64 * 68];
    gemm_body<S, XKT, WPLAIN>(zs, blockIdx.x, blockIdx.y,
                              xp, hp, Bp, bs, cst, hop, hplain);
}

// ---------------------------------------------------------------------------
// Fused encoder wave: z=0 -> l1(t-1), z=1 -> l0(t). Buffer-disjoint.
// ---------------------------------------------------------------------------
__global__ __launch_bounds__(256, 2)
void enc_wave(const unsigned char* __restrict__ xp1,   // l1: h0 stream
              const unsigned char* __restrict__ hp1,   // l1: h1 in
              const unsigned char* __restrict__ Bp1,
              const float* __restrict__ bs1,
              float* __restrict__ cst1,
              unsigned char* __restrict__ hop1,
              const unsigned char* __restrict__ xp0,   // l0: x stream
              const unsigned char* __restrict__ hp0,   // l0: h0 in
              const unsigned char* __restrict__ Bp0,
              const float* __restrict__ bs0,
              float* __restrict__ cst0,
              unsigned char* __restrict__ hop0)
{
    __shared__ float zs[64 * 68];
    if (blockIdx.z == 0)
        gemm_body<S_L1, 32, false>(zs, blockIdx.x, blockIdx.y,
                                   xp1, hp1, Bp1, bs1, cst1, hop1, nullptr);
    else
        gemm_body<S_L0, 2, false>(zs, blockIdx.x, blockIdx.y,
                                  xp0, hp0, Bp0, bs0, cst0, hop0, nullptr);
}

// ---------------------------------------------------------------------------
// Decoder heads (identical to R13)
// ---------------------------------------------------------------------------
__global__ __launch_bounds__(256)
void dec_fc(const __half* __restrict__ h1,
            const float* __restrict__ fc1_w, const float* __restrict__ fc1_b,
            const float* __restrict__ fc4_w, const float* __restrict__ fc4_b,
            float* __restrict__ out, int t)
{
    unsigned char* Dp = g_scratch + OFF_DECX;
    __shared__ float sh[HIDDEN];
    const int b = blockIdx.x;
    for (int i = threadIdx.x; i < HIDDEN; i += blockDim.x)
        sh[i] = __half2float(h1[b * HIDDEN + i]);
    __syncthreads();

    const int warp = threadIdx.x >> 5;
    const int lane = threadIdx.x & 31;
    for (int o = warp; o < 1 + NFEAT; o += 8) {
        const float* w = (o == 0) ? fc1_w : (fc4_w + (o - 1) * HIDDEN);
        float s = 0.f;
#pragma unroll 4
        for (int k = lane; k < HIDDEN; k += 32) s += sh[k] * w[k];
#pragma unroll
        for (int off = 16; off; off >>= 1) s += __shfl_down_sync(0xffffffffu, s, off);
        if (lane == 0) {
            if (o == 0) {
                out[b * HORIZONS + t] = s + fc1_b[0];
            } else {
                int f = o - 1;
                float v = s + fc4_b[f];
                int ktl = f >> 4, kk = f & 15;
                int mt = b >> 4, r = b & 15;
                int q  = ((r >> 3) & 1) + ((kk >> 3) & 1) * 2;
                int l0 = ((r & 7) << 2) + ((kk & 7) >> 1);
                unsigned char* addr = Dp + ((size_t)(mt * 2 + ktl) * 32 + l0) * 16
                                      + q * 4 + (kk & 1) * 2;
                *(__half*)addr = __float2half_rn(v);
            }
        }
    }
}

// ---------------------------------------------------------------------------
extern "C" void kernel_launch(void* const* d_in, const int* in_sizes, int n_in,
                              void* d_out, int out_size)
{
    const int wb = (in_sizes[2] == 1) ? 3 : 2;

    const float* src = (const float*)d_in[0];
    WPtrs wp;
    for (int i = 0; i < 16; i++) wp.w[i] = (const float*)d_in[wb + i];
    const float* fc1_w = (const float*)d_in[wb + 16];
    const float* fc1_b = (const float*)d_in[wb + 17];
    const float* fc4_w = (const float*)d_in[wb + 18];
    const float* fc4_b = (const float*)d_in[wb + 19];
    float* out = (float*)d_out;

    unsigned char* S = nullptr;
    cudaGetSymbolAddress((void**)&S, g_scratch);

    unsigned char* B0 = S + OFF_B0;
    unsigned char* B1 = S + OFF_B1;
    unsigned char* B2 = S + OFF_B2;
    unsigned char* B3 = S + OFF_B3;
    float* BS = (float*)(S + OFF_BS);
    unsigned char* H0PK[2] = {S + OFF_H0PK, S + OFF_H0PK + HPK_BYTES};
    unsigned char* H1PK[2] = {S + OFF_H1PK, S + OFF_H1PK + HPK_BYTES};
    float* C0 = (float*)(S + OFF_C);
    float* C1 = C0 + 512 * 512;
    unsigned char* XPK  = S + OFF_XPK;
    unsigned char* DECX = S + OFF_DECX;
    __half* H1PL = (__half*)(S + OFF_H1PL);

    // launch #1, #2 setup; #3 = l0(t=0); #4+ = fused waves (ncu -s 5 -> wave 2)
    setup_all<<<1024, 256>>>(src, wp);
    init_decx_pk<<<(32 * 2 * 128 + 255) / 256, 256>>>(src);

    dim3 grid(32, 8);        // 256 CTAs
    dim3 gridF(32, 8, 2);    // fused: 512 CTAs

    // t = 0: l0 only
    lstm_step_dl<S_L0, 2, false><<<grid, 256>>>(
        XPK, H0PK[0], B0, BS + 0 * NGATE, C0, H0PK[1], nullptr);

    // fused waves w = 1..95: l1(w-1) + l0(w)
    for (int w = 1; w < LAGS; ++w) {
        enc_wave<<<gridF, 256>>>(
            /* l1(w-1) */ H0PK[w & 1], H1PK[(w - 1) & 1], B1, BS + 1 * NGATE,
                          C1, H1PK[w & 1],
            /* l0(w)   */ XPK + (size_t)w * XPK_T, H0PK[w & 1], B0, BS + 0 * NGATE,
                          C0, H0PK[(w + 1) & 1]);
    }

    // l1(t=95)
    lstm_step_dl<S_L1, 32, false><<<grid, 256>>>(
        H0PK[0], H1PK[1], B1, BS + 1 * NGATE, C1, H1PK[0], nullptr);

    // ---- decoder (R13) ----
    for (int tt = 0; tt < HORIZONS; tt++) {
        int t = LAGS + tt;
        lstm_step_dl<S_L0, 2, false><<<grid, 256>>>(
            DECX, H0PK[t & 1], B2, BS + 2 * NGATE,
            C0, H0PK[(t + 1) & 1], nullptr);
        lstm_step_dl<S_L1, 32, true><<<grid, 256>>>(
            H0PK[(t + 1) & 1], H1PK[t & 1], B3, BS + 3 * NGATE,
            C1, H1PK[(t + 1) & 1], H1PL);
        dec_fc<<<BATCH, 256>>>(H1PL, fc1_w, fc1_b, fc4_w, fc4_b, out, tt);
    }
}

// round 17
// speedup vs baseline: 1.5076x; 1.0504x over previous
#include <cuda_runtime.h>
#include <cuda_fp16.h>
#include <cstdint>

// ---------------------------------------------------------------------------
// LSTM Seq2Seq on GB300 — R17 = R16 with the encoder wave merged INTO the CTA:
// each of 256 CTAs runs l1(w-1) then l0(w) sequentially (buffer-disjoint),
// giving one uniform CTA-wave (no 1.73-wave tail). MMA issue reordered:
// kt0 across all 4 accs, then kt1 (bit-identical per-acc order).
// Decoder unchanged from R13.
// ---------------------------------------------------------------------------

#define HIDDEN   512
#define BATCH    512
#define NFEAT    32
#define LAGS     96
#define HORIZONS 24
#define NGATE    2048

#define S_L0     17            // k32 stages, K=544
#define S_L1     32            // k32 stages, K=1024

#define BPK0_BYTES (256u * S_L0 * 512u)
#define BPK1_BYTES (256u * S_L1 * 512u)
#define HPK_BYTES  (32u * 32u * 512u)     // [mt 32][kt 32][512B]
#define XPK_T      (32u * 2u * 512u)      // [mt 32][ktl 2][512B] per timestep

// ---- scratch layout (bytes) ----
#define OFF_B0    0u
#define OFF_B1    (OFF_B0 + BPK0_BYTES)
#define OFF_B2    (OFF_B1 + BPK1_BYTES)
#define OFF_B3    (OFF_B2 + BPK0_BYTES)
#define OFF_BS    (OFF_B3 + BPK1_BYTES)            // float[4*2048]
#define OFF_H0PK  (OFF_BS + 4u * 2048u * 4u)       // 2 x HPK
#define OFF_H1PK  (OFF_H0PK + 2u * HPK_BYTES)      // 2 x HPK
#define OFF_C     (OFF_H1PK + 2u * HPK_BYTES)      // float[2*512*512]
#define OFF_XPK   (OFF_C + 2u * 512u * 512u * 4u)  // 96 x XPK_T
#define OFF_DECX  (OFF_XPK + 96u * XPK_T)          // XPK_T
#define OFF_H1PL  (OFF_DECX + XPK_T)               // half[512*512]
#define SCRATCH_BYTES (OFF_H1PL + 512u * 512u * 2u)

__device__ __align__(1024) unsigned char g_scratch[SCRATCH_BYTES];

// ---------------------------------------------------------------------------
__device__ __forceinline__ void mma_f16(float* d, const uint32_t* a,
                                        uint32_t b0, uint32_t b1) {
    asm volatile(
        "mma.sync.aligned.m16n8k16.row.col.f32.f16.f16.f32 "
        "{%0,%1,%2,%3},{%4,%5,%6,%7},{%8,%9},{%0,%1,%2,%3};"
        : "+f"(d[0]), "+f"(d[1]), "+f"(d[2]), "+f"(d[3])
        : "r"(a[0]), "r"(a[1]), "r"(a[2]), "r"(a[3]), "r"(b0), "r"(b1));
}
__device__ __forceinline__ float fsigmoid(float x) { return 1.f / (1.f + __expf(-x)); }
__device__ __forceinline__ float ftanh(float x)    { return 2.f / (1.f + __expf(-2.f * x)) - 1.f; }
__device__ __forceinline__ uint32_t h2u(float a, float b) {
    __half2 h = __floats2half2_rn(a, b);
    return *(uint32_t*)&h;
}

// ---------------------------------------------------------------------------
// Setup (launch #1): pack B (4 layers), biases, x (96 steps), zero states.
// ---------------------------------------------------------------------------
struct WPtrs { const float* w[16]; };

__global__ void setup_all(const float* __restrict__ src, WPtrs wp)
{
    unsigned char* S = g_scratch;
    const int gs   = gridDim.x * blockDim.x;
    const int tid0 = blockIdx.x * blockDim.x + threadIdx.x;

    const uint32_t boff[4]  = {OFF_B0, OFF_B1, OFF_B2, OFF_B3};
    const int      bstg[4]  = {S_L0, S_L1, S_L0, S_L1};
    const int      indim[4] = {NFEAT, HIDDEN, NFEAT, HIDDEN};

    for (int l = 0; l < 4; ++l) {
        const float* Wih = wp.w[l * 4 + 0];
        const float* Whh = wp.w[l * 4 + 1];
        unsigned char* Bp = S + boff[l];
        const int stg = bstg[l], idim = indim[l];
        const int total = 256 * stg * 128;
        for (int u = tid0; u < total; u += gs) {
            int q    = u & 3;
            int lane = (u >> 2) & 31;
            int s    = (u >> 7) % stg;
            int nt   = (u >> 7) / stg;
            int n = nt * 8 + (lane >> 2);
            int k = s * 32 + q * 8 + 2 * (lane & 3);
            int j = n >> 2, g = n & 3;
            int row = g * HIDDEN + j;
            float v0, v1;
            if (k < idim)          v0 = Wih[row * idim + k];
            else                   v0 = Whh[row * HIDDEN + (k - idim)];
            if (k + 1 < idim)      v1 = Wih[row * idim + k + 1];
            else                   v1 = Whh[row * HIDDEN + (k + 1 - idim)];
            *(uint32_t*)(Bp + ((size_t)(nt * stg + s) * 32 + lane) * 16 + q * 4) = h2u(v0, v1);
        }
        const float* bih = wp.w[l * 4 + 2];
        const float* bhh = wp.w[l * 4 + 3];
        float* BS = (float*)(S + OFF_BS);
        for (int n = tid0; n < NGATE; n += gs) {
            int j = n >> 2, g = n & 3;
            BS[l * NGATE + n] = bih[g * HIDDEN + j] + bhh[g * HIDDEN + j];
        }
    }

    {   // x fragment packing: [t][mt 32][ktl 2][lane 32][q 4]
        unsigned char* Xp = S + OFF_XPK;
        const int total = LAGS * 32 * 2 * 128;
        for (int u = tid0; u < total; u += gs) {
            int q    = u & 3;
            int lane = (u >> 2) & 31;
            int ktl  = (u >> 7) & 1;
            int mt   = (u >> 8) & 31;
            int t    = (u >> 13);
            int m = mt * 16 + (q & 1) * 8 + (lane >> 2);
            int k = ktl * 16 + (q >> 1) * 8 + 2 * (lane & 3);
            float v0 = src[m * (LAGS * NFEAT) + t * NFEAT + k];
            float v1 = src[m * (LAGS * NFEAT) + t * NFEAT + k + 1];
            *(uint32_t*)(Xp + (size_t)t * XPK_T +
                         ((size_t)(mt * 2 + ktl) * 32 + lane) * 16 + q * 4) = h2u(v0, v1);
        }
    }

    {   // zero h-packed (4 buffers), c, h1plain
        uint32_t* Z = (uint32_t*)(S + OFF_H0PK);
        int total = (4 * HPK_BYTES + 2 * 512 * 512 * 4) / 4;
        for (int i = tid0; i < total; i += gs) Z[i] = 0;
        uint32_t* P = (uint32_t*)(S + OFF_H1PL);
        for (int i = tid0; i < 512 * 512 * 2 / 4; i += gs) P[i] = 0;
    }
}

// launch #2: initial decx (packed) from src[:, 95, :]
__global__ void init_decx_pk(const float* __restrict__ src)
{
    unsigned char* Dp = g_scratch + OFF_DECX;
    int u = blockIdx.x * blockDim.x + threadIdx.x;
    if (u >= 32 * 2 * 128) return;
    int q    = u & 3;
    int lane = (u >> 2) & 31;
    int ktl  = (u >> 7) & 1;
    int mt   = (u >> 8);
    int m = mt * 16 + (q & 1) * 8 + (lane >> 2);
    int k = ktl * 16 + (q >> 1) * 8 + 2 * (lane & 3);
    float v0 = src[m * (LAGS * NFEAT) + (LAGS - 1) * NFEAT + k];
    float v1 = src[m * (LAGS * NFEAT) + (LAGS - 1) * NFEAT + k + 1];
    *(uint32_t*)(Dp + ((size_t)(mt * 2 + ktl) * 32 + lane) * 16 + q * 4) = h2u(v0, v1);
}

// ---------------------------------------------------------------------------
// Split-K mainloop half: stages [S0, S1), warp tile 32m x 32n.
// MMA order: kt0 across all 4 acc sets, then kt1 (spaces dependent pairs).
// ---------------------------------------------------------------------------
template <int S0, int S1, int XKT, int S>
__device__ __forceinline__
void run_half(const unsigned char* __restrict__ xp,
              const unsigned char* __restrict__ hp,
              const unsigned char* __restrict__ bptr,
              int mtb, int lane, float acc[2][4][4])
{
    uint4 a[2][2][2];
    uint4 b[2][4];

    auto loadS = [&](int buf, int s) {
        const int kt0 = 2 * s;
        const unsigned char* base;
        int ktl0, mts;
        if (kt0 < XKT) { base = xp; ktl0 = kt0;       mts = XKT * 512; }
        else           { base = hp; ktl0 = kt0 - XKT; mts = 32 * 512;  }
#pragma unroll
        for (int i = 0; i < 2; ++i) {
            const unsigned char* p = base + (size_t)(mtb + i) * mts + (size_t)ktl0 * 512 + lane * 16;
            a[buf][i][0] = *(const uint4*)p;
            a[buf][i][1] = *(const uint4*)(p + 512);
        }
#pragma unroll
        for (int j = 0; j < 4; ++j)
            b[buf][j] = *(const uint4*)(bptr + ((size_t)j * S + s) * 512);
    };

    loadS(0, S0);
#pragma unroll 4
    for (int i = 0; i < S1 - S0; ++i) {
        const int s  = S0 + i;
        const int cb = i & 1;
        if (s + 1 < S1) loadS(cb ^ 1, s + 1);
        // kt0 across all 8 independent accs, then kt1
#pragma unroll
        for (int mi = 0; mi < 2; ++mi)
#pragma unroll
            for (int nf = 0; nf < 4; ++nf)
                mma_f16(acc[mi][nf], (const uint32_t*)&a[cb][mi][0], b[cb][nf].x, b[cb][nf].y);
#pragma unroll
        for (int mi = 0; mi < 2; ++mi)
#pragma unroll
            for (int nf = 0; nf < 4; ++nf)
                mma_f16(acc[mi][nf], (const uint32_t*)&a[cb][mi][1], b[cb][nf].z, b[cb][nf].w);
    }
}

// ---------------------------------------------------------------------------
// GEMM + cell body (R13 split-K, as device function).
// ---------------------------------------------------------------------------
template <int S, int XKT, bool WPLAIN>
__device__ __forceinline__
void gemm_body(float* zs, int bx, int by,
               const unsigned char* __restrict__ xp,
               const unsigned char* __restrict__ hp,
               const unsigned char* __restrict__ Bp,
               const float* __restrict__ bs,
               float* __restrict__ cst,
               unsigned char* __restrict__ hop,
               __half* __restrict__ hplain)
{
    constexpr int SH = (S + 1) / 2;

    const int tid  = threadIdx.x;
    const int w    = tid >> 5, lane = tid & 31;
    const int half = w >> 2, wl = w & 3;
    const int mgrp = wl >> 1, ngrp = wl & 1;
    const int mtb  = by * 4 + mgrp * 2;
    const int ntb  = bx * 8 + ngrp * 4;
    const int g    = lane >> 2, tg = lane & 3;

    const unsigned char* bptr = Bp + ((size_t)ntb * S * 32 + lane) * 16;

    float acc[2][4][4];
#pragma unroll
    for (int i = 0; i < 2; ++i)
#pragma unroll
        for (int nf = 0; nf < 4; ++nf)
#pragma unroll
            for (int q = 0; q < 4; ++q) acc[i][nf][q] = 0.f;

    if (half == 0) run_half<0,  SH, XKT, S>(xp, hp, bptr, mtb, lane, acc);
    else           run_half<SH, S,  XKT, S>(xp, hp, bptr, mtb, lane, acc);

    if (half == 0) {
#pragma unroll
        for (int i = 0; i < 2; ++i)
#pragma unroll
            for (int nf = 0; nf < 4; ++nf) {
                int r = mgrp * 32 + i * 16 + g;
                int c = ngrp * 32 + nf * 8 + 2 * tg;
                *(float2*)&zs[r * 68 + c]       = make_float2(acc[i][nf][0], acc[i][nf][1]);
                *(float2*)&zs[(r + 8) * 68 + c] = make_float2(acc[i][nf][2], acc[i][nf][3]);
            }
    }
    __syncthreads();
    if (half == 1) {
#pragma unroll
        for (int i = 0; i < 2; ++i)
#pragma unroll
            for (int nf = 0; nf < 4; ++nf) {
                int r = mgrp * 32 + i * 16 + g;
                int c = ngrp * 32 + nf * 8 + 2 * tg;
                float2* p0 = (float2*)&zs[r * 68 + c];
                float2* p1 = (float2*)&zs[(r + 8) * 68 + c];
                float2 v0 = *p0, v1 = *p1;
                v0.x += acc[i][nf][0]; v0.y += acc[i][nf][1];
                v1.x += acc[i][nf][2]; v1.y += acc[i][nf][3];
                *p0 = v0; *p1 = v1;
            }
    }
    __syncthreads();

    {   // 256 threads: row = tid>>2 (0..63), grp = tid&3 (4 j each)
        const int row = tid >> 2;
        const int grp = tid & 3;
        const int bg  = by * 64 + row;
        const int j0  = bx * 16 + grp * 4;
        const int n0  = bx * 64 + grp * 16;

        const float* zrow = &zs[row * 68 + grp * 16];
        float4 cA = *(const float4*)&cst[bg * HIDDEN + j0];
        float cOld[4] = {cA.x, cA.y, cA.z, cA.w};
        float hv[4], cN[4];
#pragma unroll
        for (int q = 0; q < 4; ++q) {
            float4 z4 = *(const float4*)&zrow[q * 4];
            float4 b4 = *(const float4*)&bs[n0 + q * 4];
            float zi = z4.x + b4.x;
            float zf = z4.y + b4.y;
            float zg = z4.z + b4.z;
            float zo = z4.w + b4.w;
            float cn = fsigmoid(zf) * cOld[q] + fsigmoid(zi) * ftanh(zg);
            cN[q] = cn;
            hv[q] = fsigmoid(zo) * ftanh(cn);
        }
        *(float4*)&cst[bg * HIDDEN + j0] = make_float4(cN[0], cN[1], cN[2], cN[3]);

        {
            int kt = j0 >> 4, kkb = j0 & 15;
            int mt = bg >> 4, r = bg & 15;
            int q  = ((r >> 3) & 1) + ((kkb >> 3) & 1) * 2;
            int l0 = ((r & 7) << 2) + ((kkb & 7) >> 1);
            unsigned char* base = hop + ((size_t)(mt * 32 + kt) * 32 + l0) * 16 + q * 4;
            *(uint32_t*)base        = h2u(hv[0], hv[1]);
            *(uint32_t*)(base + 16) = h2u(hv[2], hv[3]);
        }
        if (WPLAIN) {
            __half2 p0 = __floats2half2_rn(hv[0], hv[1]);
            __half2 p1 = __floats2half2_rn(hv[2], hv[3]);
            *(uint2*)&hplain[bg * HIDDEN + j0] =
                make_uint2(*(uint32_t*)&p0, *(uint32_t*)&p1);
        }
    }
}

// ---------------------------------------------------------------------------
// Standalone kernel (decoder + encoder edges)
// ---------------------------------------------------------------------------
template <int S, int XKT, bool WPLAIN>
__global__ __launch_bounds__(256, 2)
void lstm_step_dl(const unsigned char* __restrict__ xp,
                  const unsigned char* __restrict__ hp,
                  const unsigned char* __restrict__ Bp,
                  const float* __restrict__ bs,
                  float* __restrict__ cst,
                  unsigned char* __restrict__ hop,
                  __half* __restrict__ hplain)
{
    __shared__ float zs[64 * 68];
    gemm_body<S, XKT, WPLAIN>(zs, blockIdx.x, blockIdx.y,
                              xp, hp, Bp, bs, cst, hop, hplain);
}

// ---------------------------------------------------------------------------
// Merged encoder wave: each CTA runs l1(w-1) then l0(w). 256 CTAs = 1 wave.
// ---------------------------------------------------------------------------
__global__ __launch_bounds__(256, 2)
void enc_wave(const unsigned char* __restrict__ xp1,   // l1: h0 stream
              const unsigned char* __restrict__ hp1,   // l1: h1 in
              const unsigned char* __restrict__ Bp1,
              const float* __restrict__ bs1,
              float* __restrict__ cst1,
              unsigned char* __restrict__ hop1,
              const unsigned char* __restrict__ xp0,   // l0: x stream
              const unsigned char* __restrict__ hp0,   // l0: h0 in
              const unsigned char* __restrict__ Bp0,
              const float* __restrict__ bs0,
              float* __restrict__ cst0,
              unsigned char* __restrict__ hop0)
{
    __shared__ float zs[64 * 68];
    gemm_body<S_L1, 32, false>(zs, blockIdx.x, blockIdx.y,
                               xp1, hp1, Bp1, bs1, cst1, hop1, nullptr);
    __syncthreads();
    gemm_body<S_L0, 2, false>(zs, blockIdx.x, blockIdx.y,
                              xp0, hp0, Bp0, bs0, cst0, hop0, nullptr);
}

// ---------------------------------------------------------------------------
// Decoder heads (identical to R13)
// ---------------------------------------------------------------------------
__global__ __launch_bounds__(256)
void dec_fc(const __half* __restrict__ h1,
            const float* __restrict__ fc1_w, const float* __restrict__ fc1_b,
            const float* __restrict__ fc4_w, const float* __restrict__ fc4_b,
            float* __restrict__ out, int t)
{
    unsigned char* Dp = g_scratch + OFF_DECX;
    __shared__ float sh[HIDDEN];
    const int b = blockIdx.x;
    for (int i = threadIdx.x; i < HIDDEN; i += blockDim.x)
        sh[i] = __half2float(h1[b * HIDDEN + i]);
    __syncthreads();

    const int warp = threadIdx.x >> 5;
    const int lane = threadIdx.x & 31;
    for (int o = warp; o < 1 + NFEAT; o += 8) {
        const float* w = (o == 0) ? fc1_w : (fc4_w + (o - 1) * HIDDEN);
        float s = 0.f;
#pragma unroll 4
        for (int k = lane; k < HIDDEN; k += 32) s += sh[k] * w[k];
#pragma unroll
        for (int off = 16; off; off >>= 1) s += __shfl_down_sync(0xffffffffu, s, off);
        if (lane == 0) {
            if (o == 0) {
                out[b * HORIZONS + t] = s + fc1_b[0];
            } else {
                int f = o - 1;
                float v = s + fc4_b[f];
                int ktl = f >> 4, kk = f & 15;
                int mt = b >> 4, r = b & 15;
                int q  = ((r >> 3) & 1) + ((kk >> 3) & 1) * 2;
                int l0 = ((r & 7) << 2) + ((kk & 7) >> 1);
                unsigned char* addr = Dp + ((size_t)(mt * 2 + ktl) * 32 + l0) * 16
                                      + q * 4 + (kk & 1) * 2;
                *(__half*)addr = __float2half_rn(v);
            }
        }
    }
}

// ---------------------------------------------------------------------------
extern "C" void kernel_launch(void* const* d_in, const int* in_sizes, int n_in,
                              void* d_out, int out_size)
{
    const int wb = (in_sizes[2] == 1) ? 3 : 2;

    const float* src = (const float*)d_in[0];
    WPtrs wp;
    for (int i = 0; i < 16; i++) wp.w[i] = (const float*)d_in[wb + i];
    const float* fc1_w = (const float*)d_in[wb + 16];
    const float* fc1_b = (const float*)d_in[wb + 17];
    const float* fc4_w = (const float*)d_in[wb + 18];
    const float* fc4_b = (const float*)d_in[wb + 19];
    float* out = (float*)d_out;

    unsigned char* S = nullptr;
    cudaGetSymbolAddress((void**)&S, g_scratch);

    unsigned char* B0 = S + OFF_B0;
    unsigned char* B1 = S + OFF_B1;
    unsigned char* B2 = S + OFF_B2;
    unsigned char* B3 = S + OFF_B3;
    float* BS = (float*)(S + OFF_BS);
    unsigned char* H0PK[2] = {S + OFF_H0PK, S + OFF_H0PK + HPK_BYTES};
    unsigned char* H1PK[2] = {S + OFF_H1PK, S + OFF_H1PK + HPK_BYTES};
    float* C0 = (float*)(S + OFF_C);
    float* C1 = C0 + 512 * 512;
    unsigned char* XPK  = S + OFF_XPK;
    unsigned char* DECX = S + OFF_DECX;
    __half* H1PL = (__half*)(S + OFF_H1PL);

    // launch #1, #2 setup; #3 = l0(t=0); #4+ = merged waves
    setup_all<<<1024, 256>>>(src, wp);
    init_decx_pk<<<(32 * 2 * 128 + 255) / 256, 256>>>(src);

    dim3 grid(32, 8);        // 256 CTAs

    // t = 0: l0 only
    lstm_step_dl<S_L0, 2, false><<<grid, 256>>>(
        XPK, H0PK[0], B0, BS + 0 * NGATE, C0, H0PK[1], nullptr);

    // merged waves w = 1..95: l1(w-1) then l0(w) per CTA
    for (int w = 1; w < LAGS; ++w) {
        enc_wave<<<grid, 256>>>(
            /* l1(w-1) */ H0PK[w & 1], H1PK[(w - 1) & 1], B1, BS + 1 * NGATE,
                          C1, H1PK[w & 1],
            /* l0(w)   */ XPK + (size_t)w * XPK_T, H0PK[w & 1], B0, BS + 0 * NGATE,
                          C0, H0PK[(w + 1) & 1]);
    }

    // l1(t=95)
    lstm_step_dl<S_L1, 32, false><<<grid, 256>>>(
        H0PK[0], H1PK[1], B1, BS + 1 * NGATE, C1, H1PK[0], nullptr);

    // ---- decoder (R13) ----
    for (int tt = 0; tt < HORIZONS; tt++) {
        int t = LAGS + tt;
        lstm_step_dl<S_L0, 2, false><<<grid, 256>>>(
            DECX, H0PK[t & 1], B2, BS + 2 * NGATE,
            C0, H0PK[(t + 1) & 1], nullptr);
        lstm_step_dl<S_L1, 32, true><<<grid, 256>>>(
            H0PK[(t + 1) & 1], H1PK[t & 1], B3, BS + 3 * NGATE,
            C1, H1PK[(t + 1) & 1], H1PL);
        dec_fc<<<BATCH, 256>>>(H1PL, fc1_w, fc1_b, fc4_w, fc4_b, out, tt);
    }
}